// round 2
// baseline (speedup 1.0000x reference)
#include <cuda_runtime.h>
#include <cuda_bf16.h>

#define IMG_H 4096
#define IMG_W 4096
#define OUT_H 4097
#define OUT_W 4097
#define TILE  32
#define HIST  35   // TILE + 3  (hist rows/cols needed: oy-2 .. oy+TILE)
#define INW   37   // TILE + 5  (hist + 1 sobel halo each side)
#define INP   40   // padded input row stride (words)
#define HP    36   // padded hist row stride (words)

// cos(pi/8), sin(pi/8) rounded to f32
#define CC 0.92387953251128674f
#define SS 0.38268343236508978f

__global__ __launch_bounds__(256, 4)
void sift_fused_kernel(const float* __restrict__ x, float* __restrict__ out)
{
    // Declared first for 16B alignment of float4 array.
    __shared__ float4        s_rs[HIST][TILE][2];   // 35*32*8 f32 = 35840 B
    __shared__ float         s_in[INW][INP];        //  5920 B
    __shared__ float         s_mag[HIST][HP];       //  5040 B
    __shared__ unsigned char s_idx[HIST][HP];       //  1260 B
    // total 48060 B < 48 KB static limit

    const int X0  = blockIdx.x * TILE;   // output tile origin
    const int Y0  = blockIdx.y * TILE;
    const int tid = threadIdx.x;

    // ---- Stage 1: load input tile (origin Y0-3, X0-3), zero-padded ----
    for (int k = tid; k < INW * INW; k += 256) {
        int r  = k / INW, c = k % INW;
        int gy = Y0 - 3 + r;
        int gx = X0 - 3 + c;
        float v = 0.0f;
        if (gy >= 0 && gy < IMG_H && gx >= 0 && gx < IMG_W)
            v = x[(size_t)gy * IMG_W + gx];
        s_in[r][c] = v;
    }
    __syncthreads();

    // ---- Stage 2: Sobel + orientation argmax + magnitude for 35x35 hist region ----
    for (int e = tid; e < HIST * HIST; e += 256) {
        int h  = e / HIST, w = e % HIST;
        int gy = Y0 - 2 + h;              // global hist row
        int gx = X0 - 2 + w;              // global hist col
        float mag = 0.0f;
        int   bi  = 0;
        if (gy >= 0 && gy < IMG_H && gx >= 0 && gx < IMG_W) {
            // input local coords: hist pixel center = s_in[h+1][w+1]
            float a00 = s_in[h    ][w], a01 = s_in[h    ][w + 1], a02 = s_in[h    ][w + 2];
            float a10 = s_in[h + 1][w],                            a12 = s_in[h + 1][w + 2];
            float a20 = s_in[h + 2][w], a21 = s_in[h + 2][w + 1], a22 = s_in[h + 2][w + 2];

            float dx = (a02 - a00) + 2.0f * (a12 - a10) + (a22 - a20);
            float dy = (a20 - a00) + 2.0f * (a21 - a01) + (a22 - a02);

            // cosines for the 8 bin centers: [p,q,r,s,-p,-q,-r,-s]
            float p = CC * dx + SS * dy;
            float q = SS * dx + CC * dy;
            float r2 = CC * dy - SS * dx;
            float s2 = SS * dy - CC * dx;

            float bv = p; bi = 0;
            if ( q  > bv) { bv =  q;  bi = 1; }
            if ( r2 > bv) { bv =  r2; bi = 2; }
            if ( s2 > bv) { bv =  s2; bi = 3; }
            if (-p  > bv) { bv = -p;  bi = 4; }
            if (-q  > bv) { bv = -q;  bi = 5; }
            if (-r2 > bv) { bv = -r2; bi = 6; }
            if (-s2 > bv) { bv = -s2; bi = 7; }

            mag = sqrtf(dx * dx + dy * dy);
        }
        s_mag[h][w] = mag;
        s_idx[h][w] = (unsigned char)bi;
    }
    __syncthreads();

    // ---- Stage 3: horizontal 4-tap row sums with one-hot scatter ----
    // rs[h][ox][c] = sum_{k=0..3} hist_c(h, ox+k)
    for (int e = tid; e < HIST * TILE; e += 256) {
        int h  = e / TILE;
        int ox = e % TILE;
        float acc0 = 0.f, acc1 = 0.f, acc2 = 0.f, acc3 = 0.f;
        float acc4 = 0.f, acc5 = 0.f, acc6 = 0.f, acc7 = 0.f;
        #pragma unroll
        for (int k = 0; k < 4; k++) {
            float m = s_mag[h][ox + k];
            int   i = s_idx[h][ox + k];
            acc0 += (i == 0) ? m : 0.f;
            acc1 += (i == 1) ? m : 0.f;
            acc2 += (i == 2) ? m : 0.f;
            acc3 += (i == 3) ? m : 0.f;
            acc4 += (i == 4) ? m : 0.f;
            acc5 += (i == 5) ? m : 0.f;
            acc6 += (i == 6) ? m : 0.f;
            acc7 += (i == 7) ? m : 0.f;
        }
        s_rs[h][ox][0] = make_float4(acc0, acc1, acc2, acc3);
        s_rs[h][ox][1] = make_float4(acc4, acc5, acc6, acc7);
    }
    __syncthreads();

    // ---- Stage 4: vertical 4-tap sum + store 8 channels ----
    const int tx = tid & 31;
    const int ty = tid >> 5;          // 0..7
    const int gx = X0 + tx;
    if (gx < OUT_W) {
        #pragma unroll
        for (int r = 0; r < 4; r++) {
            int oy = ty + 8 * r;      // 0..31
            int gy = Y0 + oy;
            if (gy < OUT_H) {
                float a0 = 0.f, a1 = 0.f, a2 = 0.f, a3 = 0.f;
                float a4 = 0.f, a5 = 0.f, a6 = 0.f, a7 = 0.f;
                #pragma unroll
                for (int k = 0; k < 4; k++) {
                    float4 lo = s_rs[oy + k][tx][0];
                    float4 hi = s_rs[oy + k][tx][1];
                    a0 += lo.x; a1 += lo.y; a2 += lo.z; a3 += lo.w;
                    a4 += hi.x; a5 += hi.y; a6 += hi.z; a7 += hi.w;
                }
                size_t base = (size_t)gy * OUT_W + gx;
                const size_t plane = (size_t)OUT_H * OUT_W;
                out[0 * plane + base] = a0;
                out[1 * plane + base] = a1;
                out[2 * plane + base] = a2;
                out[3 * plane + base] = a3;
                out[4 * plane + base] = a4;
                out[5 * plane + base] = a5;
                out[6 * plane + base] = a6;
                out[7 * plane + base] = a7;
            }
        }
    }
}

extern "C" void kernel_launch(void* const* d_in, const int* in_sizes, int n_in,
                              void* d_out, int out_size)
{
    const float* x   = (const float*)d_in[0];
    float*       out = (float*)d_out;
    dim3 grid((OUT_W + TILE - 1) / TILE, (OUT_H + TILE - 1) / TILE);  // 129 x 129
    sift_fused_kernel<<<grid, 256>>>(x, out);
}

// round 3
// speedup vs baseline: 1.8563x; 1.8563x over previous
#include <cuda_runtime.h>
#include <cuda_bf16.h>

#define IMG_H 4096
#define IMG_W 4096
#define OUT_H 4097
#define OUT_W 4097
#define TILE  32
#define HIST  35   // TILE + 3
#define INW   37   // HIST + 2 (sobel halo)
#define INP   38   // padded input row stride (words)
#define HP    36   // padded mag/idx row stride

// cos(pi/8), sin(pi/8)
#define CC 0.92387953251128674f
#define SS 0.38268343236508978f

__device__ __forceinline__ void hist_pix(const float* s_in, int h, int w,
                                         float& mag, int& bi)
{
    const float* c = s_in + h * INP + w;
    float a00 = c[0],       a01 = c[1],           a02 = c[2];
    float a10 = c[INP],                            a12 = c[INP + 2];
    float a20 = c[2 * INP], a21 = c[2 * INP + 1], a22 = c[2 * INP + 2];

    float dx = (a02 - a00) + 2.0f * (a12 - a10) + (a22 - a20);
    float dy = (a20 - a00) + 2.0f * (a21 - a01) + (a22 - a02);

    float p  = CC * dx + SS * dy;
    float q  = SS * dx + CC * dy;
    float r2 = CC * dy - SS * dx;
    float s2 = SS * dy - CC * dx;

    float bv = p; bi = 0;
    if ( q  > bv) { bv =  q;  bi = 1; }
    if ( r2 > bv) { bv =  r2; bi = 2; }
    if ( s2 > bv) { bv =  s2; bi = 3; }
    if (-p  > bv) { bv = -p;  bi = 4; }
    if (-q  > bv) { bv = -q;  bi = 5; }
    if (-r2 > bv) { bv = -r2; bi = 6; }
    if (-s2 > bv) { bv = -s2; bi = 7; }

    mag = sqrtf(dx * dx + dy * dy);
}

__device__ __forceinline__ float4 f4add(float4 a, float4 b) {
    return make_float4(a.x + b.x, a.y + b.y, a.z + b.z, a.w + b.w);
}
__device__ __forceinline__ float4 f4addsub(float4 a, float4 p, float4 m) {
    return make_float4(a.x + p.x - m.x, a.y + p.y - m.y,
                       a.z + p.z - m.z, a.w + p.w - m.w);
}

__global__ __launch_bounds__(256, 5)
void sift_fused_kernel(const float* __restrict__ x, float* __restrict__ out)
{
    // rs transposed: [chan-group][hist row][x]  -> lane(x) contiguous float4
    __shared__ float4        s_rs[2][HIST][TILE];   // 35840 B (aliased as input tile)
    __shared__ float         s_mag[HIST][HP];       //  5040 B
    __shared__ unsigned char s_idx[HIST][HP];       //  1260 B
    // total 42140 B -> 5 CTAs/SM

    float* s_in = (float*)s_rs;   // [INW][INP] = 5624 B, dead after stage 2

    const int X0   = blockIdx.x * TILE;
    const int Y0   = blockIdx.y * TILE;
    const int tid  = threadIdx.x;
    const int lane = tid & 31;
    const int wrow = tid >> 5;    // 0..7

    const bool interior =
        blockIdx.x >= 1 && blockIdx.x <= 126 &&
        blockIdx.y >= 1 && blockIdx.y <= 126;

    // ---- Stage 1: load input tile (origin Y0-3, X0-3) ----
    if (interior) {
        const float* src = x + (size_t)(Y0 - 3) * IMG_W + (X0 - 3);
        #pragma unroll
        for (int it = 0; it < 5; ++it) {
            int r = wrow + 8 * it;
            if (r < INW) {
                const float* row = src + (size_t)r * IMG_W;
                s_in[r * INP + lane] = row[lane];
                if (lane < INW - 32)
                    s_in[r * INP + 32 + lane] = row[32 + lane];
            }
        }
    } else {
        #pragma unroll
        for (int it = 0; it < 5; ++it) {
            int r = wrow + 8 * it;
            if (r < INW) {
                int  gy    = Y0 - 3 + r;
                bool rowok = (gy >= 0) && (gy < IMG_H);
                int  gx    = X0 - 3 + lane;
                float v = 0.0f;
                if (rowok && gx >= 0 && gx < IMG_W)
                    v = x[(size_t)gy * IMG_W + gx];
                s_in[r * INP + lane] = v;
                if (lane < INW - 32) {
                    int gx2 = gx + 32;
                    float v2 = 0.0f;
                    if (rowok && gx2 >= 0 && gx2 < IMG_W)
                        v2 = x[(size_t)gy * IMG_W + gx2];
                    s_in[r * INP + 32 + lane] = v2;
                }
            }
        }
    }
    __syncthreads();

    // ---- Stage 2: Sobel + argmax bin + magnitude over 35x35 hist region ----
    if (interior) {
        #pragma unroll
        for (int it = 0; it < 5; ++it) {
            int h = wrow + 8 * it;
            if (h < HIST) {
                float mag; int bi;
                hist_pix(s_in, h, lane, mag, bi);
                s_mag[h][lane] = mag;
                s_idx[h][lane] = (unsigned char)bi;
            }
        }
        if (tid < HIST) {
            #pragma unroll
            for (int w = 32; w < HIST; ++w) {
                float mag; int bi;
                hist_pix(s_in, tid, w, mag, bi);
                s_mag[tid][w] = mag;
                s_idx[tid][w] = (unsigned char)bi;
            }
        }
    } else {
        #pragma unroll
        for (int it = 0; it < 5; ++it) {
            int h = wrow + 8 * it;
            if (h < HIST) {
                int gy = Y0 - 2 + h;
                int gx = X0 - 2 + lane;
                float mag = 0.0f; int bi = 0;
                if (gy >= 0 && gy < IMG_H && gx >= 0 && gx < IMG_W)
                    hist_pix(s_in, h, lane, mag, bi);
                s_mag[h][lane] = mag;
                s_idx[h][lane] = (unsigned char)bi;
            }
        }
        if (tid < HIST) {
            #pragma unroll
            for (int w = 32; w < HIST; ++w) {
                int gy = Y0 - 2 + tid;
                int gx = X0 - 2 + w;
                float mag = 0.0f; int bi = 0;
                if (gy >= 0 && gy < IMG_H && gx >= 0 && gx < IMG_W)
                    hist_pix(s_in, tid, w, mag, bi);
                s_mag[tid][w] = mag;
                s_idx[tid][w] = (unsigned char)bi;
            }
        }
    }
    __syncthreads();

    // ---- Stage 3: horizontal 4-tap row sums with one-hot scatter ----
    // rs[c][h][x] = sum_{k=0..3} hist_c(h, x+k)
    #pragma unroll
    for (int it = 0; it < 5; ++it) {
        int e = tid + 256 * it;
        if (e < HIST * TILE) {
            int h  = e >> 5;
            int ox = e & 31;
            float a0 = 0.f, a1 = 0.f, a2 = 0.f, a3 = 0.f;
            float a4 = 0.f, a5 = 0.f, a6 = 0.f, a7 = 0.f;
            #pragma unroll
            for (int k = 0; k < 4; k++) {
                float m = s_mag[h][ox + k];
                int   i = s_idx[h][ox + k];
                if (i == 0) a0 += m;
                if (i == 1) a1 += m;
                if (i == 2) a2 += m;
                if (i == 3) a3 += m;
                if (i == 4) a4 += m;
                if (i == 5) a5 += m;
                if (i == 6) a6 += m;
                if (i == 7) a7 += m;
            }
            s_rs[0][h][ox] = make_float4(a0, a1, a2, a3);
            s_rs[1][h][ox] = make_float4(a4, a5, a6, a7);
        }
    }
    __syncthreads();

    // ---- Stage 4: vertical 4-tap sliding sum + store 8 channels ----
    const int    gx    = X0 + lane;
    const size_t plane = (size_t)OUT_H * OUT_W;
    const int    oy0   = wrow * 4;          // 4 consecutive rows per thread

    float4 lo = f4add(f4add(s_rs[0][oy0][lane],     s_rs[0][oy0 + 1][lane]),
                      f4add(s_rs[0][oy0 + 2][lane], s_rs[0][oy0 + 3][lane]));
    float4 hi = f4add(f4add(s_rs[1][oy0][lane],     s_rs[1][oy0 + 1][lane]),
                      f4add(s_rs[1][oy0 + 2][lane], s_rs[1][oy0 + 3][lane]));

    #pragma unroll
    for (int r = 0; r < 4; r++) {
        if (r > 0) {
            lo = f4addsub(lo, s_rs[0][oy0 + r + 3][lane], s_rs[0][oy0 + r - 1][lane]);
            hi = f4addsub(hi, s_rs[1][oy0 + r + 3][lane], s_rs[1][oy0 + r - 1][lane]);
        }
        int gy = Y0 + oy0 + r;
        if (gy < OUT_H && gx < OUT_W) {
            size_t base = (size_t)gy * OUT_W + gx;
            out[0 * plane + base] = lo.x;
            out[1 * plane + base] = lo.y;
            out[2 * plane + base] = lo.z;
            out[3 * plane + base] = lo.w;
            out[4 * plane + base] = hi.x;
            out[5 * plane + base] = hi.y;
            out[6 * plane + base] = hi.z;
            out[7 * plane + base] = hi.w;
        }
    }
}

extern "C" void kernel_launch(void* const* d_in, const int* in_sizes, int n_in,
                              void* d_out, int out_size)
{
    const float* x   = (const float*)d_in[0];
    float*       out = (float*)d_out;
    dim3 grid((OUT_W + TILE - 1) / TILE, (OUT_H + TILE - 1) / TILE);  // 129 x 129
    sift_fused_kernel<<<grid, 256>>>(x, out);
}